// round 2
// baseline (speedup 1.0000x reference)
#include <cuda_runtime.h>
#include <math_constants.h>

// Problem constants
#define BB 64
#define HH 224
#define WW 224
#define CC 196
#define HWP (HH*WW)
#define NEIGH 10

// ---------------- static scratch (no allocations allowed) ----------------
__device__ float         g_wg  [BB*HWP];   // (grad^4)*10
__device__ float         g_cpU [BB*HWP];   // sum_c |col[y,x]-col[(y+1)%H,x]| * 10
__device__ float         g_cpL [BB*HWP];   // sum_c |col[y,x]-col[y,(x+1)%W]| * 10
__device__ float         g_distA[BB*HWP];
__device__ float         g_distB[BB*HWP];
__device__ unsigned char g_maskA[BB*HWP];
__device__ unsigned char g_maskB[BB*HWP];
__device__ float         g_minval[BB*CC];
__device__ int           g_minidx[BB*CC];
__device__ int           g_centi [BB*CC*2];   // integer centroids for seeding

// ---------------- Phase 1a: per-(batch,centroid) window min/argmin ----------------
// One warp per (b,c). Finds min value over the 20x20 window and the FIRST
// (row-major) flat index attaining it (occupied-dedup handled in phase 1b).
__global__ void minima_kernel(const float* __restrict__ g) {
    int gw   = (blockIdx.x * blockDim.x + threadIdx.x) >> 5;
    int lane = threadIdx.x & 31;
    if (gw >= BB * CC) return;
    int b = gw / CC, c = gw - b * CC;
    int y0 = 8 + 16 * (c / 14);
    int x0 = 8 + 16 * (c % 14);
    int ymin = max(0, y0 - NEIGH), ymax = min(HH, y0 + NEIGH);
    int xmin = max(0, x0 - NEIGH), xmax = min(WW, x0 + NEIGH);
    int wh = ymax - ymin, ww = xmax - xmin, n = wh * ww;
    const float* gb = g + (size_t)b * HWP;

    float bv = CUDART_INF_F;
    int   bi = 0x7fffffff;
    for (int k = lane; k < n; k += 32) {
        int y = ymin + k / ww;
        int x = xmin + k - (k / ww) * ww;
        int f = y * WW + x;
        float v = gb[f];
        if (v < bv || (v == bv && f < bi)) { bv = v; bi = f; }
    }
    #pragma unroll
    for (int off = 16; off; off >>= 1) {
        float ov = __shfl_down_sync(0xffffffffu, bv, off);
        int   oi = __shfl_down_sync(0xffffffffu, bi, off);
        if (ov < bv || (ov == bv && oi < bi)) { bv = ov; bi = oi; }
    }
    if (lane == 0) { g_minval[gw] = bv; g_minidx[gw] = bi; }
}

// ---------------- Phase 1b: sequential occupied-dedup per batch ----------------
// One thread per batch. Replicates the reference scan exactly: if the candidate
// pixel is already occupied, rescan the window row-major for the first
// equal-to-min unoccupied pixel; if none, the centroid stays at its grid pos.
// Writes float32 coords to d_out and int coords to g_centi for seeding.
__global__ void resolve_kernel(const float* __restrict__ g, float* __restrict__ out_cents) {
    int b = blockIdx.x * blockDim.x + threadIdx.x;
    if (b >= BB) return;
    const float* gb = g + (size_t)b * HWP;
    int pos[CC];
    int np = 0;
    for (int c = 0; c < CC; c++) {
        int y0 = 8 + 16 * (c / 14);
        int x0 = 8 + 16 * (c % 14);
        float mv = g_minval[b * CC + c];
        int   mi = g_minidx[b * CC + c];
        bool occ = false;
        for (int i = 0; i < np; i++) if (pos[i] == mi) { occ = true; break; }
        int chosen = mi;
        bool found = true;
        if (occ) {
            found = false;
            int ymin = max(0, y0 - NEIGH), ymax = min(HH, y0 + NEIGH);
            int xmin = max(0, x0 - NEIGH), xmax = min(WW, x0 + NEIGH);
            for (int y = ymin; y < ymax && !found; y++) {
                for (int x = xmin; x < xmax; x++) {
                    int f = y * WW + x;
                    if (gb[f] == mv) {
                        bool o2 = false;
                        for (int i = 0; i < np; i++) if (pos[i] == f) { o2 = true; break; }
                        if (!o2) { chosen = f; found = true; break; }
                    }
                }
            }
        }
        int cy, cx;
        if (found) { pos[np++] = chosen; cy = chosen / WW; cx = chosen - cy * WW; }
        else       { cy = y0; cx = x0; }
        g_centi[(b * CC + c) * 2 + 0] = cy;
        g_centi[(b * CC + c) * 2 + 1] = cx;
        out_cents[(b * CC + c) * 2 + 0] = (float)cy;
        out_cents[(b * CC + c) * 2 + 1] = (float)cx;
    }
}

// ---------------- Phase 2: precompute weighted grad + color penalties ----------------
__global__ void maps_kernel(const float* __restrict__ xin, const float* __restrict__ g) {
    int i = blockIdx.x * blockDim.x + threadIdx.x;
    if (i >= BB * HWP) return;
    int b = i / HWP;
    int r = i - b * HWP;
    int y = r / WW;
    int x = r - y * WW;

    float gv = g[i];
    float t = gv * gv;
    g_wg[i] = (t * t) * 10.0f;

    const float* cb = xin + (size_t)b * 3 * HWP;
    int yn = (y + 1 == HH) ? 0 : y + 1;
    int xn = (x + 1 == WW) ? 0 : x + 1;
    int rU = yn * WW + x;
    int rL = y * WW + xn;
    float su = 0.0f, sl = 0.0f;
    #pragma unroll
    for (int ch = 0; ch < 3; ch++) {
        float v = cb[ch * HWP + r];
        su += fabsf(v - cb[ch * HWP + rU]);
        sl += fabsf(v - cb[ch * HWP + rL]);
    }
    g_cpU[i] = su * 10.0f;
    g_cpL[i] = sl * 10.0f;
}

// ---------------- Phase 3a: init + seed ----------------
__global__ void init_kernel() {
    int i = blockIdx.x * blockDim.x + threadIdx.x;
    if (i >= BB * HWP) return;
    g_distA[i] = CUDART_INF_F;
    g_maskA[i] = 255;
}

// Sequential per batch so duplicate centroid pixels resolve "later label wins"
__global__ void seed_kernel() {
    int b = blockIdx.x * blockDim.x + threadIdx.x;
    if (b >= BB) return;
    for (int c = 0; c < CC; c++) {
        int y = g_centi[(b * CC + c) * 2 + 0];
        int x = g_centi[(b * CC + c) * 2 + 1];
        int idx = b * HWP + y * WW + x;
        g_distA[idx] = 0.0f;
        g_maskA[idx] = (unsigned char)c;
    }
}

// ---------------- Phase 3b: one directional Jacobi pass (double buffered) ----------------
// D=0: up    (reads (y+1)%H), cp = cpU[i]
// D=1: down  (reads (y-1)%H), cp = cpU[nidx]
// D=2: left  (reads (x+1)%W), cp = cpL[i]
// D=3: right (reads (x-1)%W), cp = cpL[nidx]
template <int D>
__global__ void pass_kernel(int ab) {
    int i = blockIdx.x * blockDim.x + threadIdx.x;
    if (i >= BB * HWP) return;
    const float*         din  = ab ? g_distB : g_distA;
    float*               dout = ab ? g_distA : g_distB;
    const unsigned char* min_ = ab ? g_maskB : g_maskA;
    unsigned char*       mout = ab ? g_maskA : g_maskB;

    int b = i / HWP;
    int r = i - b * HWP;
    int y = r / WW;
    int x = r - y * WW;

    int ny = y, nx = x;
    if (D == 0) ny = (y + 1 == HH) ? 0 : y + 1;
    if (D == 1) ny = (y == 0) ? HH - 1 : y - 1;
    if (D == 2) nx = (x + 1 == WW) ? 0 : x + 1;
    if (D == 3) nx = (x == 0) ? WW - 1 : x - 1;
    int nidx = b * HWP + ny * WW + nx;

    float nd  = din[nidx];
    float wgv = g_wg[i];
    float cp;
    if (D == 0)      cp = g_cpU[i];
    else if (D == 1) cp = g_cpU[nidx];
    else if (D == 2) cp = g_cpL[i];
    else             cp = g_cpL[nidx];

    float wd = (nd + wgv) + cp;   // matches reference add order
    float dc = din[i];
    if (wd < dc) { dout[i] = wd; mout[i] = min_[nidx]; }
    else         { dout[i] = dc; mout[i] = min_[i]; }
}

// ---------------- finalize: u8 mask -> float32 with 255 -> -1.0f ----------------
__global__ void finalize_kernel(float* __restrict__ out_mask, int ab) {
    int i = blockIdx.x * blockDim.x + threadIdx.x;
    if (i >= BB * HWP) return;
    const unsigned char* m = ab ? g_maskB : g_maskA;
    unsigned char v = m[i];
    out_mask[i] = (v == 255) ? -1.0f : (float)v;
}

// ---------------- launch ----------------
extern "C" void kernel_launch(void* const* d_in, const int* in_sizes, int n_in,
                              void* d_out, int out_size) {
    const float* x;
    const float* g;
    if (in_sizes[0] == BB * 3 * HWP) { x = (const float*)d_in[0]; g = (const float*)d_in[1]; }
    else                             { x = (const float*)d_in[1]; g = (const float*)d_in[0]; }

    float* out = (float*)d_out;
    float* out_cents;   // [B, C, 2] as float32
    float* out_mask;    // [B, H, W] as float32

    if (out_size >= BB * CC * 2 + BB * HWP) {
        out_cents = out;                // tuple order: cents first
        out_mask  = out + BB * CC * 2;
    } else if (out_size == BB * HWP) {
        out_cents = (float*)g_minval;   // dummy sink (unused region ok, overwritten later is fine
        // NOTE: g_minval is too small; use a dedicated dummy: reuse g_distB head? It is
        // rewritten after resolve anyway? No — resolve runs before init. Use g_wg head:
        out_cents = g_wg;               // g_wg written AFTER resolve by maps_kernel, safe order? resolve->maps overwrites. OK.
        out_mask  = out;
    } else {                            // cents only
        out_cents = out;
        out_mask  = g_wg;               // dummy sink, rewritten semantics not needed
    }

    const int NPX = BB * HWP;
    const int TPB = 256;
    const int GPX = (NPX + TPB - 1) / TPB;

    minima_kernel<<<(BB * CC * 32 + TPB - 1) / TPB, TPB>>>(g);
    resolve_kernel<<<1, 64>>>(g, out_cents);
    maps_kernel<<<GPX, TPB>>>(x, g);
    init_kernel<<<GPX, TPB>>>();
    seed_kernel<<<1, 64>>>();

    int ab = 0; // 0: current state in A buffers
    for (int it = 0; it < 50; it++) {
        pass_kernel<0><<<GPX, TPB>>>(ab); ab ^= 1;
        pass_kernel<1><<<GPX, TPB>>>(ab); ab ^= 1;
        pass_kernel<2><<<GPX, TPB>>>(ab); ab ^= 1;
        pass_kernel<3><<<GPX, TPB>>>(ab); ab ^= 1;
    }
    finalize_kernel<<<GPX, TPB>>>(out_mask, ab);
}

// round 3
// speedup vs baseline: 27.2723x; 27.2723x over previous
#include <cuda_runtime.h>
#include <math_constants.h>

// Problem constants
#define BB 64
#define HH 224
#define WW 224
#define CC 196
#define HWP (HH*WW)
#define NEIGH 10

// Fused-pass tiling: K iterations (4 directions each) per kernel, halo = K.
#define TILE 32
#define KIT 2
#define HALO 2
#define TF (TILE + 2*HALO)      // 36
#define TT (TF*TF)              // 1296
#define NT 256
#define NTILES 7                // 224/32
#define TPIMG (NTILES*NTILES)   // 49

// ---------------- static scratch ----------------
__device__ float  g_wg  [BB*HWP];   // (grad^4)*10
__device__ float  g_cpU [BB*HWP];   // 10*sum_c |col(y,x)-col((y+1)%H,x)|
__device__ float  g_cpL [BB*HWP];   // 10*sum_c |col(y,x)-col(y,(x+1)%W)|
__device__ float2 g_stA [BB*HWP];   // (dist, label)
__device__ float2 g_stB [BB*HWP];
__device__ float  g_minval[BB*CC];
__device__ int    g_minidx[BB*CC];
__device__ int    g_centi [BB*CC*2];

// ---------------- Phase 1a: per-(batch,centroid) window min + first argmin ----------------
__global__ void minima_kernel(const float* __restrict__ g) {
    int gw   = (blockIdx.x * blockDim.x + threadIdx.x) >> 5;
    int lane = threadIdx.x & 31;
    if (gw >= BB * CC) return;
    int b = gw / CC, c = gw - b * CC;
    int y0 = 8 + 16 * (c / 14);
    int x0 = 8 + 16 * (c % 14);
    int ymin = max(0, y0 - NEIGH), ymax = min(HH, y0 + NEIGH);
    int xmin = max(0, x0 - NEIGH), xmax = min(WW, x0 + NEIGH);
    int wh = ymax - ymin, ww = xmax - xmin, n = wh * ww;
    const float* gb = g + (size_t)b * HWP;

    float bv = CUDART_INF_F;
    int   bi = 0x7fffffff;
    for (int k = lane; k < n; k += 32) {
        int ky = k / ww;
        int y = ymin + ky;
        int x = xmin + (k - ky * ww);
        int f = y * WW + x;
        float v = gb[f];
        if (v < bv || (v == bv && f < bi)) { bv = v; bi = f; }
    }
    #pragma unroll
    for (int off = 16; off; off >>= 1) {
        float ov = __shfl_down_sync(0xffffffffu, bv, off);
        int   oi = __shfl_down_sync(0xffffffffu, bi, off);
        if (ov < bv || (ov == bv && oi < bi)) { bv = ov; bi = oi; }
    }
    if (lane == 0) { g_minval[gw] = bv; g_minidx[gw] = bi; }
}

// ---------------- Phase 1b: occupied-dedup, one warp-block per batch ----------------
// smem bitmap gives O(1) membership; rescan is warp-parallel (ballot picks the
// first row-major equal-to-min unoccupied pixel, matching torch.nonzero order).
__global__ void resolve_kernel(const float* __restrict__ g, float* __restrict__ out_cents) {
    __shared__ unsigned int occ[(HWP + 31) / 32];   // 1568 words
    int b    = blockIdx.x;
    int lane = threadIdx.x;
    for (int i = lane; i < (HWP + 31) / 32; i += 32) occ[i] = 0u;
    __syncwarp();
    const float* gb = g + (size_t)b * HWP;

    for (int c = 0; c < CC; c++) {
        float mv = g_minval[b * CC + c];
        int   mi = g_minidx[b * CC + c];
        int y0c = 8 + 16 * (c / 14);
        int x0c = 8 + 16 * (c % 14);
        bool isocc = (occ[mi >> 5] >> (mi & 31)) & 1u;
        int  chosen = mi;
        bool found  = true;
        if (isocc) {
            found = false;
            int ymin = max(0, y0c - NEIGH), ymax = min(HH, y0c + NEIGH);
            int xmin = max(0, x0c - NEIGH), xmax = min(WW, x0c + NEIGH);
            int wwid = xmax - xmin, n = (ymax - ymin) * wwid;
            for (int base = 0; base < n; base += 32) {
                int k = base + lane;
                bool m = false; int f = 0;
                if (k < n) {
                    int ky = k / wwid;
                    int yy = ymin + ky;
                    int xx = xmin + (k - ky * wwid);
                    f = yy * WW + xx;
                    m = (gb[f] == mv) && !((occ[f >> 5] >> (f & 31)) & 1u);
                }
                unsigned bal = __ballot_sync(0xffffffffu, m);
                if (bal) {
                    int first = __ffs(bal) - 1;
                    chosen = __shfl_sync(0xffffffffu, f, first);
                    found = true;
                    break;
                }
            }
        }
        int cy, cx;
        if (found) {
            if (lane == 0) occ[chosen >> 5] |= 1u << (chosen & 31);
            cy = chosen / WW; cx = chosen - cy * WW;
        } else {
            cy = y0c; cx = x0c;
        }
        __syncwarp();
        if (lane == 0) {
            g_centi[(b * CC + c) * 2 + 0] = cy;
            g_centi[(b * CC + c) * 2 + 1] = cx;
            out_cents[(b * CC + c) * 2 + 0] = (float)cy;
            out_cents[(b * CC + c) * 2 + 1] = (float)cx;
        }
    }
}

// ---------------- Phase 2: weighted grad + per-direction color penalties ----------------
__global__ void maps_kernel(const float* __restrict__ xin, const float* __restrict__ g) {
    int i = blockIdx.x * blockDim.x + threadIdx.x;
    if (i >= BB * HWP) return;
    int b = i / HWP;
    int r = i - b * HWP;
    int y = r / WW;
    int x = r - y * WW;

    float gv = g[i];
    float t = gv * gv;
    g_wg[i] = (t * t) * 10.0f;

    const float* cb = xin + (size_t)b * 3 * HWP;
    int yn = (y + 1 == HH) ? 0 : y + 1;
    int xn = (x + 1 == WW) ? 0 : x + 1;
    int rU = yn * WW + x;
    int rL = y * WW + xn;
    float su = 0.0f, sl = 0.0f;
    #pragma unroll
    for (int ch = 0; ch < 3; ch++) {
        float v = cb[ch * HWP + r];
        su += fabsf(v - cb[ch * HWP + rU]);
        sl += fabsf(v - cb[ch * HWP + rL]);
    }
    g_cpU[i] = su * 10.0f;
    g_cpL[i] = sl * 10.0f;
}

// ---------------- Phase 3a: init + seed ----------------
__global__ void init_kernel() {
    int i = blockIdx.x * blockDim.x + threadIdx.x;
    if (i >= BB * HWP) return;
    g_stA[i] = make_float2(CUDART_INF_F, -1.0f);
}

__global__ void seed_kernel() {   // sequential per batch: later label wins on dup pixels
    int b = blockIdx.x * blockDim.x + threadIdx.x;
    if (b >= BB) return;
    for (int c = 0; c < CC; c++) {
        int y = g_centi[(b * CC + c) * 2 + 0];
        int x = g_centi[(b * CC + c) * 2 + 1];
        g_stA[b * HWP + y * WW + x] = make_float2(0.0f, (float)c);
    }
}

// ---------------- Phase 3b: fused KIT iterations (4*KIT directional steps) ----------------
// Step order U,D,L,R. U reads (y+1)%H w/ cpU[self]; D reads (y-1)%H w/ cpU[nb];
// L reads (x+1)%W w/ cpL[self]; R reads (x-1)%W w/ cpL[nb].
// Valid region shrinks 1 ring per iteration; exact bounds per step below.
__global__ __launch_bounds__(NT) void fused_pass_kernel(int ab) {
    __shared__ float2 st[2][TT];
    __shared__ float  wgs[TT], cpus[TT], cpls[TT];

    const float2* __restrict__ in  = ab ? g_stB : g_stA;
    float2*       __restrict__ out = ab ? g_stA : g_stB;

    int blk = blockIdx.x;
    int b   = blk / TPIMG;
    int t   = blk - b * TPIMG;
    int ty  = t / NTILES, tx = t - ty * NTILES;
    int y0  = ty * TILE - HALO;
    int x0  = tx * TILE - HALO;
    int bb  = b * HWP;
    int tid = threadIdx.x;

    // load tile + halo (toroidal wrap)
    for (int p = tid; p < TT; p += NT) {
        int r = p / TF, c = p - r * TF;
        int gy = y0 + r; if (gy < 0) gy += HH; else if (gy >= HH) gy -= HH;
        int gx = x0 + c; if (gx < 0) gx += WW; else if (gx >= WW) gx -= WW;
        int gi = bb + gy * WW + gx;
        st[0][p] = in[gi];
        wgs[p]  = g_wg[gi];
        cpus[p] = g_cpU[gi];
        cpls[p] = g_cpL[gi];
    }
    __syncthreads();

    int cur = 0;
    #pragma unroll
    for (int s = 0; s < 4 * KIT; s++) {
        const int d  = s & 3;
        const int it = s >> 2;
        const int rlo = (d == 0) ? it : it + 1;
        const int rhi = TF - 1 - it;
        const int clo = (d == 3) ? it + 1 : it;
        const int chi = (d >= 2) ? TF - 1 - it : TF - it;
        const int nxt = cur ^ 1;
        for (int p = tid; p < TT; p += NT) {
            int r = p / TF, c = p - r * TF;
            if (r < rlo || r >= rhi || c < clo || c >= chi) continue;
            int nb = (d == 0) ? p + TF : (d == 1) ? p - TF : (d == 2) ? p + 1 : p - 1;
            float2 self = st[cur][p];
            float2 nbv  = st[cur][nb];
            float  w    = wgs[p];
            float  cp   = (d == 0) ? cpus[p] : (d == 1) ? cpus[nb]
                        : (d == 2) ? cpls[p] : cpls[nb];
            float wd = (nbv.x + w) + cp;       // exact reference add order
            st[nxt][p] = (wd < self.x) ? make_float2(wd, nbv.y) : self;
        }
        __syncthreads();
        cur = nxt;
    }

    // store interior
    for (int p = tid; p < TT; p += NT) {
        int r = p / TF, c = p - r * TF;
        if (r < HALO || r >= TF - HALO || c < HALO || c >= TF - HALO) continue;
        out[bb + (y0 + r) * WW + (x0 + c)] = st[cur][p];
    }
}

// ---------------- finalize ----------------
__global__ void finalize_kernel(float* __restrict__ out_mask, int ab) {
    int i = blockIdx.x * blockDim.x + threadIdx.x;
    if (i >= BB * HWP) return;
    const float2* st = ab ? g_stB : g_stA;
    out_mask[i] = st[i].y;
}

// ---------------- launch ----------------
extern "C" void kernel_launch(void* const* d_in, const int* in_sizes, int n_in,
                              void* d_out, int out_size) {
    const float* x;
    const float* g;
    if (in_sizes[0] == BB * 3 * HWP) { x = (const float*)d_in[0]; g = (const float*)d_in[1]; }
    else                             { x = (const float*)d_in[1]; g = (const float*)d_in[0]; }

    float* out       = (float*)d_out;
    float* out_cents = out;               // [B, C, 2] float32
    float* out_mask  = out + BB * CC * 2; // [B, H, W] float32

    const int NPX = BB * HWP;
    const int TPB = 256;
    const int GPX = (NPX + TPB - 1) / TPB;

    minima_kernel<<<(BB * CC * 32 + TPB - 1) / TPB, TPB>>>(g);
    resolve_kernel<<<BB, 32>>>(g, out_cents);
    maps_kernel<<<GPX, TPB>>>(x, g);
    init_kernel<<<GPX, TPB>>>();
    seed_kernel<<<1, 64>>>();

    int ab = 0;   // 0: current state in A
    const int NKERN = 50 / (2 * KIT) * 2;     // 25 fused launches of KIT=2 iterations
    for (int k = 0; k < NKERN; k++) {
        fused_pass_kernel<<<BB * TPIMG, NT>>>(ab);
        ab ^= 1;
    }
    finalize_kernel<<<GPX, TPB>>>(out_mask, ab);
}

// round 5
// speedup vs baseline: 27.5252x; 1.0093x over previous
#include <cuda_runtime.h>
#include <math_constants.h>

// Problem constants
#define BB 64
#define HH 224
#define WW 224
#define CC 196
#define HWP (HH*WW)
#define NEIGH 10

// Band tiling: full-width bands, vertical halo only.
#define TFY   28            // tile rows (interior + 2*KIT halo)
#define KIT   5             // iterations fused per launch
#define BR    18            // interior rows per band (TFY - 2*KIT)
#define BANDS 13            // ceil(224/18)
#define SW    225           // padded float row stride (bank-conflict-free both phases)
#define SLW   228           // padded byte row stride for labels
#define NT    224           // 7 warps: 224 columns / 28 rows x 8 segs
#define SEGW  28            // horizontal segment width
#define SMEM_BYTES (4*TFY*SW*4 + TFY*SLW)   // sd+wg+cpU+cpL floats + labels

// ---------------- static scratch ----------------
__device__ float         g_wg [BB*HWP];
__device__ float         g_cpU[BB*HWP];
__device__ float         g_cpL[BB*HWP];
__device__ float         g_dA [BB*HWP];
__device__ float         g_dB [BB*HWP];
__device__ unsigned char g_lA [BB*HWP];
__device__ unsigned char g_lB [BB*HWP];
__device__ float         g_minval[BB*CC];
__device__ int           g_minidx[BB*CC];
__device__ int           g_centi [BB*CC*2];

// ---------------- Phase 1a: window min + first argmin ----------------
__global__ void minima_kernel(const float* __restrict__ g) {
    int gw   = (blockIdx.x * blockDim.x + threadIdx.x) >> 5;
    int lane = threadIdx.x & 31;
    if (gw >= BB * CC) return;
    int b = gw / CC, c = gw - b * CC;
    int y0 = 8 + 16 * (c / 14);
    int x0 = 8 + 16 * (c % 14);
    int ymin = max(0, y0 - NEIGH), ymax = min(HH, y0 + NEIGH);
    int xmin = max(0, x0 - NEIGH), xmax = min(WW, x0 + NEIGH);
    int ww = xmax - xmin, n = (ymax - ymin) * ww;
    const float* gb = g + (size_t)b * HWP;

    float bv = CUDART_INF_F;
    int   bi = 0x7fffffff;
    for (int k = lane; k < n; k += 32) {
        int ky = k / ww;
        int f = (ymin + ky) * WW + xmin + (k - ky * ww);
        float v = gb[f];
        if (v < bv || (v == bv && f < bi)) { bv = v; bi = f; }
    }
    #pragma unroll
    for (int off = 16; off; off >>= 1) {
        float ov = __shfl_down_sync(0xffffffffu, bv, off);
        int   oi = __shfl_down_sync(0xffffffffu, bi, off);
        if (ov < bv || (ov == bv && oi < bi)) { bv = ov; bi = oi; }
    }
    if (lane == 0) { g_minval[gw] = bv; g_minidx[gw] = bi; }
}

// ---------------- Phase 1b: occupied-dedup, one warp per batch ----------------
__global__ void resolve_kernel(const float* __restrict__ g, float* __restrict__ out_cents) {
    __shared__ unsigned int occ[(HWP + 31) / 32];
    int b    = blockIdx.x;
    int lane = threadIdx.x;
    for (int i = lane; i < (HWP + 31) / 32; i += 32) occ[i] = 0u;
    __syncwarp();
    const float* gb = g + (size_t)b * HWP;

    for (int c = 0; c < CC; c++) {
        float mv = g_minval[b * CC + c];
        int   mi = g_minidx[b * CC + c];
        int y0c = 8 + 16 * (c / 14);
        int x0c = 8 + 16 * (c % 14);
        bool isocc = (occ[mi >> 5] >> (mi & 31)) & 1u;
        int  chosen = mi;
        bool found  = true;
        if (isocc) {
            found = false;
            int ymin = max(0, y0c - NEIGH), ymax = min(HH, y0c + NEIGH);
            int xmin = max(0, x0c - NEIGH), xmax = min(WW, x0c + NEIGH);
            int wwid = xmax - xmin, n = (ymax - ymin) * wwid;
            for (int base = 0; base < n; base += 32) {
                int k = base + lane;
                bool m = false; int f = 0;
                if (k < n) {
                    int ky = k / wwid;
                    f = (ymin + ky) * WW + xmin + (k - ky * wwid);
                    m = (gb[f] == mv) && !((occ[f >> 5] >> (f & 31)) & 1u);
                }
                unsigned bal = __ballot_sync(0xffffffffu, m);
                if (bal) {
                    chosen = __shfl_sync(0xffffffffu, f, __ffs(bal) - 1);
                    found = true;
                    break;
                }
            }
        }
        int cy, cx;
        if (found) {
            if (lane == 0) occ[chosen >> 5] |= 1u << (chosen & 31);
            cy = chosen / WW; cx = chosen - cy * WW;
        } else { cy = y0c; cx = x0c; }
        __syncwarp();
        if (lane == 0) {
            g_centi[(b * CC + c) * 2 + 0] = cy;
            g_centi[(b * CC + c) * 2 + 1] = cx;
            out_cents[(b * CC + c) * 2 + 0] = (float)cy;
            out_cents[(b * CC + c) * 2 + 1] = (float)cx;
        }
    }
}

// ---------------- Phase 2: weighted grad + color penalties ----------------
__global__ void maps_kernel(const float* __restrict__ xin, const float* __restrict__ g) {
    int i = blockIdx.x * blockDim.x + threadIdx.x;
    if (i >= BB * HWP) return;
    int b = i / HWP;
    int r = i - b * HWP;
    int y = r / WW;
    int x = r - y * WW;

    float gv = g[i];
    float t = gv * gv;
    g_wg[i] = (t * t) * 10.0f;

    const float* cb = xin + (size_t)b * 3 * HWP;
    int yn = (y + 1 == HH) ? 0 : y + 1;
    int xn = (x + 1 == WW) ? 0 : x + 1;
    int rU = yn * WW + x;
    int rL = y * WW + xn;
    float su = 0.0f, sl = 0.0f;
    #pragma unroll
    for (int ch = 0; ch < 3; ch++) {
        float v = cb[ch * HWP + r];
        su += fabsf(v - cb[ch * HWP + rU]);
        sl += fabsf(v - cb[ch * HWP + rL]);
    }
    g_cpU[i] = su * 10.0f;
    g_cpL[i] = sl * 10.0f;
}

// ---------------- Phase 3a: init + seed ----------------
__global__ void init_kernel() {
    int i = blockIdx.x * blockDim.x + threadIdx.x;
    if (i >= BB * HWP) return;
    g_dA[i] = CUDART_INF_F;
    g_lA[i] = 255;
}

__global__ void seed_kernel() {   // sequential per batch: later label wins
    int b = blockIdx.x * blockDim.x + threadIdx.x;
    if (b >= BB) return;
    for (int c = 0; c < CC; c++) {
        int y = g_centi[(b * CC + c) * 2 + 0];
        int x = g_centi[(b * CC + c) * 2 + 1];
        int idx = b * HWP + y * WW + x;
        g_dA[idx] = 0.0f;
        g_lA[idx] = (unsigned char)c;
    }
}

// ---------------- Phase 3b: KIT fused iterations, in-place ordered sweeps ----------------
// U: reads (y+1)%H, cp=cpU[self]  -> process ascending y  (nb not yet written)
// D: reads (y-1)%H, cp=cpU[nb]    -> process descending y
// L: reads (x+1)%W, cp=cpL[self]  -> process ascending x
// R: reads (x-1)%W, cp=cpL[nb]    -> process descending x
// Register carry supplies the old self value, so the in-place sweep is
// bit-exact Jacobi with the reference add order (nd + wg) + cp.
__global__ __launch_bounds__(NT) void fused_pass_kernel(int ab) {
    extern __shared__ unsigned char smem_raw[];
    float*         sd  = (float*)smem_raw;                  // TFY*SW
    float*         swg = sd  + TFY * SW;
    float*         scU = swg + TFY * SW;
    float*         scL = scU + TFY * SW;
    unsigned char* slb = (unsigned char*)(scL + TFY * SW);  // TFY*SLW

    const float*         din = ab ? g_dB : g_dA;
    float*               dout = ab ? g_dA : g_dB;
    const unsigned char* lin = ab ? g_lB : g_lA;
    unsigned char*       lout = ab ? g_lA : g_lB;

    int band = blockIdx.x;
    int b    = blockIdx.y;
    int bb   = b * HWP;
    int y0   = band * BR - KIT;
    int tid  = threadIdx.x;

    // ---- load tile (toroidal wrap in y) ----
    for (int p = tid; p < TFY * WW; p += NT) {
        int r = p / WW, c = p - r * WW;
        int gy = y0 + r; if (gy < 0) gy += HH; else if (gy >= HH) gy -= HH;
        int gi = bb + gy * WW + c;
        sd [r * SW  + c] = din[gi];
        slb[r * SLW + c] = lin[gi];
        swg[r * SW  + c] = g_wg [gi];
        scU[r * SW  + c] = g_cpU[gi];
        scL[r * SW  + c] = g_cpL[gi];
    }
    __syncthreads();

    const int row = tid >> 3;          // horizontal phase: row, segment
    const int seg = tid & 7;
    const int xs  = seg * SEGW;
    const int xe  = (seg == 7) ? 0 : xs + SEGW;       // right boundary (wrapped)
    const int xw  = (seg == 0) ? WW - 1 : xs - 1;     // left boundary (wrapped)

    for (int i = 0; i < KIT; i++) {
        // ---- vertical: thread = column ----
        {
            const int t  = tid;
            const int lo = i, hi = TFY - 1 - i;
            // U ascending, rows [lo, hi)
            float ds = sd[lo * SW + t];
            unsigned char ls = slb[lo * SLW + t];
            #pragma unroll 4
            for (int r = lo; r < hi; r++) {
                float dn = sd[(r + 1) * SW + t];
                unsigned char ln = slb[(r + 1) * SLW + t];
                float wd = (dn + swg[r * SW + t]) + scU[r * SW + t];
                if (wd < ds) { ds = wd; ls = ln; }
                sd[r * SW + t] = ds; slb[r * SLW + t] = ls;
                ds = dn; ls = ln;
            }
            // D descending, rows [i+1, hi)
            ds = sd[(hi - 1) * SW + t];
            ls = slb[(hi - 1) * SLW + t];
            #pragma unroll 4
            for (int r = hi - 1; r >= i + 1; r--) {
                float dn = sd[(r - 1) * SW + t];
                unsigned char ln = slb[(r - 1) * SLW + t];
                float wd = (dn + swg[r * SW + t]) + scU[(r - 1) * SW + t];
                if (wd < ds) { ds = wd; ls = ln; }
                sd[r * SW + t] = ds; slb[r * SLW + t] = ls;
                ds = dn; ls = ln;
            }
        }
        __syncthreads();

        const bool act = (row >= i + 1) && (row < TFY - 1 - i);
        // ---- L: pre-read right boundary, then ascending sweep ----
        float bd = 0.0f; unsigned char bl = 0;
        if (act) { bd = sd[row * SW + xe]; bl = slb[row * SLW + xe]; }
        __syncthreads();
        if (act) {
            float ds = sd[row * SW + xs];
            unsigned char ls = slb[row * SLW + xs];
            #pragma unroll 4
            for (int k = 0; k < SEGW; k++) {
                int x = xs + k;
                float dn         = (k < SEGW - 1) ? sd [row * SW  + x + 1] : bd;
                unsigned char ln = (k < SEGW - 1) ? slb[row * SLW + x + 1] : bl;
                float wd = (dn + swg[row * SW + x]) + scL[row * SW + x];
                if (wd < ds) { ds = wd; ls = ln; }
                sd[row * SW + x] = ds; slb[row * SLW + x] = ls;
                ds = dn; ls = ln;
            }
        }
        __syncthreads();
        // ---- R: pre-read left boundary (post-L), then descending sweep ----
        if (act) { bd = sd[row * SW + xw]; bl = slb[row * SLW + xw]; }
        __syncthreads();
        if (act) {
            float ds = sd[row * SW + xs + SEGW - 1];
            unsigned char ls = slb[row * SLW + xs + SEGW - 1];
            #pragma unroll 4
            for (int k = SEGW - 1; k >= 0; k--) {
                int x = xs + k;
                float dn         = (k > 0) ? sd [row * SW  + x - 1] : bd;
                unsigned char ln = (k > 0) ? slb[row * SLW + x - 1] : bl;
                int xn = (x == 0) ? WW - 1 : x - 1;
                float wd = (dn + swg[row * SW + x]) + scL[row * SW + xn];
                if (wd < ds) { ds = wd; ls = ln; }
                sd[row * SW + x] = ds; slb[row * SLW + x] = ls;
                ds = dn; ls = ln;
            }
        }
        __syncthreads();
    }

    // ---- store interior rows [KIT, KIT+brA) ----
    int brA = min(BR, HH - band * BR);
    for (int p = tid; p < brA * WW; p += NT) {
        int r = p / WW, c = p - r * WW;
        int gi = bb + (band * BR + r) * WW + c;
        dout[gi] = sd [(KIT + r) * SW  + c];
        lout[gi] = slb[(KIT + r) * SLW + c];
    }
}

// ---------------- finalize ----------------
__global__ void finalize_kernel(float* __restrict__ out_mask, int ab) {
    int i = blockIdx.x * blockDim.x + threadIdx.x;
    if (i >= BB * HWP) return;
    const unsigned char* l = ab ? g_lB : g_lA;
    unsigned char v = l[i];
    out_mask[i] = (v == 255) ? -1.0f : (float)v;
}

// ---------------- launch ----------------
extern "C" void kernel_launch(void* const* d_in, const int* in_sizes, int n_in,
                              void* d_out, int out_size) {
    const float* x;
    const float* g;
    if (in_sizes[0] == BB * 3 * HWP) { x = (const float*)d_in[0]; g = (const float*)d_in[1]; }
    else                             { x = (const float*)d_in[1]; g = (const float*)d_in[0]; }

    float* out       = (float*)d_out;
    float* out_cents = out;               // [B, C, 2] float32
    float* out_mask  = out + BB * CC * 2; // [B, H, W] float32

    const int NPX = BB * HWP;
    const int TPB = 256;
    const int GPX = (NPX + TPB - 1) / TPB;

    cudaFuncSetAttribute(fused_pass_kernel,
                         cudaFuncAttributeMaxDynamicSharedMemorySize, SMEM_BYTES);

    minima_kernel<<<(BB * CC * 32 + TPB - 1) / TPB, TPB>>>(g);
    resolve_kernel<<<BB, 32>>>(g, out_cents);
    maps_kernel<<<GPX, TPB>>>(x, g);
    init_kernel<<<GPX, TPB>>>();
    seed_kernel<<<1, 64>>>();

    int ab = 0;   // 0: current state in A
    for (int k = 0; k < 50 / KIT; k++) {
        fused_pass_kernel<<<dim3(BANDS, BB), NT, SMEM_BYTES>>>(ab);
        ab ^= 1;
    }
    finalize_kernel<<<GPX, TPB>>>(out_mask, ab);
}

// round 8
// speedup vs baseline: 37.2999x; 1.3551x over previous
#include <cuda_runtime.h>
#include <math_constants.h>

// Problem constants
#define BB 64
#define HH 224
#define WW 224
#define CC 196
#define HWP (HH*WW)
#define NEIGH 10

// Register-resident band tiling
#define TFY   28            // rows per thread (interior + 2*KIT halo)
#define KIT   5             // iterations fused per launch
#define BR    18            // interior rows per band
#define BANDS 13            // ceil(224/18)
#define NT    224           // thread = column
#define NW    7             // warps per block
#define NLAB  7             // packed label regs (4 rows each)

// ---------------- static scratch ----------------
__device__ float         g_wg [BB*HWP];
__device__ float         g_cpU[BB*HWP];
__device__ float         g_cpL[BB*HWP];
__device__ float         g_dA [BB*HWP];
__device__ float         g_dB [BB*HWP];
__device__ unsigned char g_lA [BB*HWP];
__device__ unsigned char g_lB [BB*HWP];
__device__ float         g_minval[BB*CC];
__device__ int           g_minidx[BB*CC];
__device__ int           g_centi [BB*CC*2];

// ---------------- Phase 1a: window min + first argmin ----------------
__global__ void minima_kernel(const float* __restrict__ g) {
    int gw   = (blockIdx.x * blockDim.x + threadIdx.x) >> 5;
    int lane = threadIdx.x & 31;
    if (gw >= BB * CC) return;
    int b = gw / CC, c = gw - b * CC;
    int y0 = 8 + 16 * (c / 14);
    int x0 = 8 + 16 * (c % 14);
    int ymin = max(0, y0 - NEIGH), ymax = min(HH, y0 + NEIGH);
    int xmin = max(0, x0 - NEIGH), xmax = min(WW, x0 + NEIGH);
    int ww = xmax - xmin, n = (ymax - ymin) * ww;
    const float* gb = g + (size_t)b * HWP;

    float bv = CUDART_INF_F;
    int   bi = 0x7fffffff;
    for (int k = lane; k < n; k += 32) {
        int ky = k / ww;
        int f = (ymin + ky) * WW + xmin + (k - ky * ww);
        float v = gb[f];
        if (v < bv || (v == bv && f < bi)) { bv = v; bi = f; }
    }
    #pragma unroll
    for (int off = 16; off; off >>= 1) {
        float ov = __shfl_down_sync(0xffffffffu, bv, off);
        int   oi = __shfl_down_sync(0xffffffffu, bi, off);
        if (ov < bv || (ov == bv && oi < bi)) { bv = ov; bi = oi; }
    }
    if (lane == 0) { g_minval[gw] = bv; g_minidx[gw] = bi; }
}

// ---------------- Phase 1b: occupied-dedup, one warp per batch ----------------
__global__ void resolve_kernel(const float* __restrict__ g, float* __restrict__ out_cents) {
    __shared__ unsigned int occ[(HWP + 31) / 32];
    int b    = blockIdx.x;
    int lane = threadIdx.x;
    for (int i = lane; i < (HWP + 31) / 32; i += 32) occ[i] = 0u;
    __syncwarp();
    const float* gb = g + (size_t)b * HWP;

    for (int c = 0; c < CC; c++) {
        float mv = g_minval[b * CC + c];
        int   mi = g_minidx[b * CC + c];
        int y0c = 8 + 16 * (c / 14);
        int x0c = 8 + 16 * (c % 14);
        bool isocc = (occ[mi >> 5] >> (mi & 31)) & 1u;
        int  chosen = mi;
        bool found  = true;
        if (isocc) {
            found = false;
            int ymin = max(0, y0c - NEIGH), ymax = min(HH, y0c + NEIGH);
            int xmin = max(0, x0c - NEIGH), xmax = min(WW, x0c + NEIGH);
            int wwid = xmax - xmin, n = (ymax - ymin) * wwid;
            for (int base = 0; base < n; base += 32) {
                int k = base + lane;
                bool m = false; int f = 0;
                if (k < n) {
                    int ky = k / wwid;
                    f = (ymin + ky) * WW + xmin + (k - ky * wwid);
                    m = (gb[f] == mv) && !((occ[f >> 5] >> (f & 31)) & 1u);
                }
                unsigned bal = __ballot_sync(0xffffffffu, m);
                if (bal) {
                    chosen = __shfl_sync(0xffffffffu, f, __ffs(bal) - 1);
                    found = true;
                    break;
                }
            }
        }
        int cy, cx;
        if (found) {
            if (lane == 0) occ[chosen >> 5] |= 1u << (chosen & 31);
            cy = chosen / WW; cx = chosen - cy * WW;
        } else { cy = y0c; cx = x0c; }
        __syncwarp();
        if (lane == 0) {
            g_centi[(b * CC + c) * 2 + 0] = cy;
            g_centi[(b * CC + c) * 2 + 1] = cx;
            out_cents[(b * CC + c) * 2 + 0] = (float)cy;
            out_cents[(b * CC + c) * 2 + 1] = (float)cx;
        }
    }
}

// ---------------- Phase 2: maps + init (fused) ----------------
__global__ void maps_kernel(const float* __restrict__ xin, const float* __restrict__ g) {
    int i = blockIdx.x * blockDim.x + threadIdx.x;
    if (i >= BB * HWP) return;
    int b = i / HWP;
    int r = i - b * HWP;
    int y = r / WW;
    int x = r - y * WW;

    float gv = g[i];
    float t = gv * gv;
    g_wg[i] = (t * t) * 10.0f;

    const float* cb = xin + (size_t)b * 3 * HWP;
    int yn = (y + 1 == HH) ? 0 : y + 1;
    int xn = (x + 1 == WW) ? 0 : x + 1;
    int rU = yn * WW + x;
    int rL = y * WW + xn;
    float su = 0.0f, sl = 0.0f;
    #pragma unroll
    for (int ch = 0; ch < 3; ch++) {
        float v = cb[ch * HWP + r];
        su += fabsf(v - cb[ch * HWP + rU]);
        sl += fabsf(v - cb[ch * HWP + rL]);
    }
    g_cpU[i] = su * 10.0f;
    g_cpL[i] = sl * 10.0f;

    g_dA[i] = CUDART_INF_F;     // init fused here
    g_lA[i] = 255;
}

__global__ void seed_kernel() {   // sequential per batch: later label wins
    int b = blockIdx.x * blockDim.x + threadIdx.x;
    if (b >= BB) return;
    for (int c = 0; c < CC; c++) {
        int y = g_centi[(b * CC + c) * 2 + 0];
        int x = g_centi[(b * CC + c) * 2 + 1];
        int idx = b * HWP + y * WW + x;
        g_dA[idx] = 0.0f;
        g_lA[idx] = (unsigned char)c;
    }
}

// ---------------- packed-label helpers (fold with unrolled q) ----------------
__device__ __forceinline__ unsigned getb(const unsigned* lab, int q) {
    return (lab[q >> 2] >> ((q & 3) * 8)) & 0xFFu;
}
__device__ __forceinline__ void setb(unsigned* lab, int q, unsigned v) {
    int sh = (q & 3) * 8;
    lab[q >> 2] = (lab[q >> 2] & ~(0xFFu << sh)) | (v << sh);
}

// ---------------- Phase 3: KIT fused iterations, register-resident columns ----------------
// Thread = column. Vertical (U,D) passes are pure-register Jacobi
// (ascending/descending order => neighbor value still old). Horizontal (L,R)
// passes get the neighbor column via __shfl; warp boundaries exchange through
// a small double-buffered smem array. Exact reference add order (nd+wg)+cp.
template <bool LAST>
__global__ __launch_bounds__(NT, 2) void fused_reg_kernel(int ab, float* __restrict__ out_mask) {
    __shared__ float    sLd[2][NW][TFY];   // lane-0 dist (pre-L)  for L pass
    __shared__ unsigned sLl[2][NW][NLAB];
    __shared__ float    sRd[2][NW][TFY];   // lane-31 dist (post-L) for R pass
    __shared__ unsigned sRl[2][NW][NLAB];
    __shared__ float    sRcL[NW][TFY];     // lane-31 cpL (constant)

    const float*         din  = ab ? g_dB : g_dA;
    float*               dout = ab ? g_dA : g_dB;
    const unsigned char* lin  = ab ? g_lB : g_lA;
    unsigned char*       lout = ab ? g_lA : g_lB;

    const int x    = threadIdx.x;
    const int lane = x & 31;
    const int wq   = x >> 5;
    const int wqn  = (wq + 1) % NW;        // right neighbor warp (for L)
    const int wqp  = (wq + NW - 1) % NW;   // left neighbor warp (for R)
    const int band = blockIdx.x;
    const int b    = blockIdx.y;
    const int bb   = b * HWP;
    const int y0   = band * BR - KIT;

    float    dist[TFY], wg[TFY], cU[TFY], cL[TFY];
    unsigned lab[NLAB];

    // ---- load (coalesced: fixed row, lanes = consecutive columns) ----
    #pragma unroll
    for (int r = 0; r < TFY; r++) {
        int gy = y0 + r; if (gy < 0) gy += HH; else if (gy >= HH) gy -= HH;
        int gi = bb + gy * WW + x;
        dist[r] = din[gi];
        wg[r]   = g_wg [gi];
        cU[r]   = g_cpU[gi];
        cL[r]   = g_cpL[gi];
        unsigned lv = lin[gi];
        if ((r & 3) == 0) lab[r >> 2] = lv;
        else              lab[r >> 2] |= lv << ((r & 3) * 8);
    }
    if (lane == 31) {
        #pragma unroll
        for (int r = 0; r < TFY; r++) sRcL[wq][r] = cL[r];
    }

    for (int i = 0; i < KIT; i++) {
        const int pb = i & 1;
        // ---- U: rows [i, TFY-1-i), ascending (reads r+1 old) ----
        #pragma unroll
        for (int r = 0; r < TFY - 1; r++) {
            if (r >= i && r < TFY - 1 - i) {
                float wd = (dist[r + 1] + wg[r]) + cU[r];
                if (wd < dist[r]) { dist[r] = wd; setb(lab, r, getb(lab, r + 1)); }
            }
        }
        // ---- D: rows [i+1, TFY-1-i), descending (reads r-1 old) ----
        #pragma unroll
        for (int rr = 0; rr < TFY - 2; rr++) {
            int r = TFY - 2 - rr;
            if (r >= i + 1 && r < TFY - 1 - i) {
                float wd = (dist[r - 1] + wg[r]) + cU[r - 1];
                if (wd < dist[r]) { dist[r] = wd; setb(lab, r, getb(lab, r - 1)); }
            }
        }

        // ---- L boundary write (pre-L lane-0 state), sync ----
        if (lane == 0) {
            #pragma unroll
            for (int r = 0; r < TFY; r++) sLd[pb][wq][r] = dist[r];
            #pragma unroll
            for (int k = 0; k < NLAB; k++) sLl[pb][wq][k] = lab[k];
        }
        __syncthreads();
        // ---- L: reads column x+1 (old), rows [i+1, TFY-1-i) ----
        {
            unsigned nlab[NLAB];
            #pragma unroll
            for (int k = 0; k < NLAB; k++) {
                nlab[k] = __shfl_down_sync(0xffffffffu, lab[k], 1);
                if (lane == 31) nlab[k] = sLl[pb][wqn][k];
            }
            #pragma unroll
            for (int r = 1; r < TFY - 1; r++) {
                float nd = __shfl_down_sync(0xffffffffu, dist[r], 1);
                if (r >= i + 1 && r < TFY - 1 - i) {
                    if (lane == 31) nd = sLd[pb][wqn][r];
                    float wd = (nd + wg[r]) + cL[r];
                    if (wd < dist[r]) { dist[r] = wd; setb(lab, r, getb(nlab, r)); }
                }
            }
        }
        // ---- R boundary write (post-L lane-31 state), sync ----
        if (lane == 31) {
            #pragma unroll
            for (int r = 0; r < TFY; r++) sRd[pb][wq][r] = dist[r];
            #pragma unroll
            for (int k = 0; k < NLAB; k++) sRl[pb][wq][k] = lab[k];
        }
        __syncthreads();
        // ---- R: reads column x-1 (post-L), cp = cpL[x-1], rows [i+1, TFY-1-i) ----
        {
            unsigned nlab[NLAB];
            #pragma unroll
            for (int k = 0; k < NLAB; k++) {
                nlab[k] = __shfl_up_sync(0xffffffffu, lab[k], 1);
                if (lane == 0) nlab[k] = sRl[pb][wqp][k];
            }
            #pragma unroll
            for (int r = 1; r < TFY - 1; r++) {
                float nd  = __shfl_up_sync(0xffffffffu, dist[r], 1);
                float ncl = __shfl_up_sync(0xffffffffu, cL[r], 1);
                if (r >= i + 1 && r < TFY - 1 - i) {
                    if (lane == 0) { nd = sRd[pb][wqp][r]; ncl = sRcL[wqp][r]; }
                    float wd = (nd + wg[r]) + ncl;
                    if (wd < dist[r]) { dist[r] = wd; setb(lab, r, getb(nlab, r)); }
                }
            }
        }
    }

    // ---- store interior rows [KIT, KIT+BR) (clipped at image edge) ----
    #pragma unroll
    for (int r = 0; r < BR; r++) {
        int gy = band * BR + r;
        if (gy < HH) {
            int gi = bb + gy * WW + x;
            unsigned v = getb(lab, KIT + r);
            if (LAST) {
                out_mask[gi] = (v == 255u) ? -1.0f : (float)v;
            } else {
                dout[gi] = dist[KIT + r];
                lout[gi] = (unsigned char)v;
            }
        }
    }
}

// ---------------- launch ----------------
extern "C" void kernel_launch(void* const* d_in, const int* in_sizes, int n_in,
                              void* d_out, int out_size) {
    const float* x;
    const float* g;
    if (in_sizes[0] == BB * 3 * HWP) { x = (const float*)d_in[0]; g = (const float*)d_in[1]; }
    else                             { x = (const float*)d_in[1]; g = (const float*)d_in[0]; }

    float* out       = (float*)d_out;
    float* out_cents = out;               // [B, C, 2] float32
    float* out_mask  = out + BB * CC * 2; // [B, H, W] float32

    const int NPX = BB * HWP;
    const int TPB = 256;
    const int GPX = (NPX + TPB - 1) / TPB;

    minima_kernel<<<(BB * CC * 32 + TPB - 1) / TPB, TPB>>>(g);
    resolve_kernel<<<BB, 32>>>(g, out_cents);
    maps_kernel<<<GPX, TPB>>>(x, g);
    seed_kernel<<<1, 64>>>();

    int ab = 0;   // 0: current state in A
    const int NLAUNCH = 50 / KIT;   // 10
    for (int k = 0; k < NLAUNCH - 1; k++) {
        fused_reg_kernel<false><<<dim3(BANDS, BB), NT>>>(ab, out_mask);
        ab ^= 1;
    }
    fused_reg_kernel<true><<<dim3(BANDS, BB), NT>>>(ab, out_mask);
}

// round 11
// speedup vs baseline: 38.8876x; 1.0426x over previous
#include <cuda_runtime.h>
#include <math_constants.h>

// Problem constants
#define BB 64
#define HH 224
#define WW 224
#define CC 196
#define HWP (HH*WW)
#define NEIGH 10

// Register-resident band tiling
#define TFY   28            // rows per thread (interior + 2*KIT halo)
#define KIT   5             // iterations fused per launch
#define BR    18            // interior rows per band
#define BANDS 13            // ceil(224/18)
#define NT    224           // thread = column
#define NW    7             // warps per block
#define NLAB  7             // packed label regs (4 rows each)
#define DYN_SMEM (2 * TFY * NT * (int)sizeof(float))   // scU + scL tiles: 50176 B

// ---------------- static scratch ----------------
__device__ float         g_wg [BB*HWP];
__device__ float         g_cpU[BB*HWP];
__device__ float         g_cpL[BB*HWP];
__device__ float         g_dA [BB*HWP];
__device__ float         g_dB [BB*HWP];
__device__ unsigned char g_lA [BB*HWP];
__device__ unsigned char g_lB [BB*HWP];
__device__ float         g_minval[BB*CC];
__device__ int           g_minidx[BB*CC];
__device__ int           g_centi [BB*CC*2];

// ---------------- Phase 1a: window min + first argmin ----------------
__global__ void minima_kernel(const float* __restrict__ g) {
    int gw   = (blockIdx.x * blockDim.x + threadIdx.x) >> 5;
    int lane = threadIdx.x & 31;
    if (gw >= BB * CC) return;
    int b = gw / CC, c = gw - b * CC;
    int y0 = 8 + 16 * (c / 14);
    int x0 = 8 + 16 * (c % 14);
    int ymin = max(0, y0 - NEIGH), ymax = min(HH, y0 + NEIGH);
    int xmin = max(0, x0 - NEIGH), xmax = min(WW, x0 + NEIGH);
    int ww = xmax - xmin, n = (ymax - ymin) * ww;
    const float* gb = g + (size_t)b * HWP;

    float bv = CUDART_INF_F;
    int   bi = 0x7fffffff;
    for (int k = lane; k < n; k += 32) {
        int ky = k / ww;
        int f = (ymin + ky) * WW + xmin + (k - ky * ww);
        float v = gb[f];
        if (v < bv || (v == bv && f < bi)) { bv = v; bi = f; }
    }
    #pragma unroll
    for (int off = 16; off; off >>= 1) {
        float ov = __shfl_down_sync(0xffffffffu, bv, off);
        int   oi = __shfl_down_sync(0xffffffffu, bi, off);
        if (ov < bv || (ov == bv && oi < bi)) { bv = ov; bi = oi; }
    }
    if (lane == 0) { g_minval[gw] = bv; g_minidx[gw] = bi; }
}

// ---------------- Phase 1b: occupied-dedup, one warp per batch ----------------
__global__ void resolve_kernel(const float* __restrict__ g, float* __restrict__ out_cents) {
    __shared__ unsigned int occ[(HWP + 31) / 32];
    int b    = blockIdx.x;
    int lane = threadIdx.x;
    for (int i = lane; i < (HWP + 31) / 32; i += 32) occ[i] = 0u;
    __syncwarp();
    const float* gb = g + (size_t)b * HWP;

    for (int c = 0; c < CC; c++) {
        float mv = g_minval[b * CC + c];
        int   mi = g_minidx[b * CC + c];
        int y0c = 8 + 16 * (c / 14);
        int x0c = 8 + 16 * (c % 14);
        bool isocc = (occ[mi >> 5] >> (mi & 31)) & 1u;
        int  chosen = mi;
        bool found  = true;
        if (isocc) {
            found = false;
            int ymin = max(0, y0c - NEIGH), ymax = min(HH, y0c + NEIGH);
            int xmin = max(0, x0c - NEIGH), xmax = min(WW, x0c + NEIGH);
            int wwid = xmax - xmin, n = (ymax - ymin) * wwid;
            for (int base = 0; base < n; base += 32) {
                int k = base + lane;
                bool m = false; int f = 0;
                if (k < n) {
                    int ky = k / wwid;
                    f = (ymin + ky) * WW + xmin + (k - ky * wwid);
                    m = (gb[f] == mv) && !((occ[f >> 5] >> (f & 31)) & 1u);
                }
                unsigned bal = __ballot_sync(0xffffffffu, m);
                if (bal) {
                    chosen = __shfl_sync(0xffffffffu, f, __ffs(bal) - 1);
                    found = true;
                    break;
                }
            }
        }
        int cy, cx;
        if (found) {
            if (lane == 0) occ[chosen >> 5] |= 1u << (chosen & 31);
            cy = chosen / WW; cx = chosen - cy * WW;
        } else { cy = y0c; cx = x0c; }
        __syncwarp();
        if (lane == 0) {
            g_centi[(b * CC + c) * 2 + 0] = cy;
            g_centi[(b * CC + c) * 2 + 1] = cx;
            out_cents[(b * CC + c) * 2 + 0] = (float)cy;
            out_cents[(b * CC + c) * 2 + 1] = (float)cx;
        }
    }
}

// ---------------- Phase 2: maps + init (fused) ----------------
__global__ void maps_kernel(const float* __restrict__ xin, const float* __restrict__ g) {
    int i = blockIdx.x * blockDim.x + threadIdx.x;
    if (i >= BB * HWP) return;
    int b = i / HWP;
    int r = i - b * HWP;
    int y = r / WW;
    int x = r - y * WW;

    float gv = g[i];
    float t = gv * gv;
    g_wg[i] = (t * t) * 10.0f;

    const float* cb = xin + (size_t)b * 3 * HWP;
    int yn = (y + 1 == HH) ? 0 : y + 1;
    int xn = (x + 1 == WW) ? 0 : x + 1;
    int rU = yn * WW + x;
    int rL = y * WW + xn;
    float su = 0.0f, sl = 0.0f;
    #pragma unroll
    for (int ch = 0; ch < 3; ch++) {
        float v = cb[ch * HWP + r];
        su += fabsf(v - cb[ch * HWP + rU]);
        sl += fabsf(v - cb[ch * HWP + rL]);
    }
    g_cpU[i] = su * 10.0f;
    g_cpL[i] = sl * 10.0f;

    g_dA[i] = CUDART_INF_F;     // init fused here
    g_lA[i] = 255;
}

// Parallel seed: one thread per (b,c). Collision-free: resolve guarantees
// chosen pixels are unique per batch (occupied bitmap), and fallback positions
// are window centers which no other window (centers >=16 px apart, radius 10)
// can reach.
__global__ void seed_kernel() {
    int i = blockIdx.x * blockDim.x + threadIdx.x;
    if (i >= BB * CC) return;
    int y = g_centi[i * 2 + 0];
    int x = g_centi[i * 2 + 1];
    int b = i / CC;
    int idx = b * HWP + y * WW + x;
    g_dA[idx] = 0.0f;
    g_lA[idx] = (unsigned char)(i - b * CC);
}

// ---------------- packed-label helpers (fold with unrolled q) ----------------
__device__ __forceinline__ unsigned getb(const unsigned* lab, int q) {
    return (lab[q >> 2] >> ((q & 3) * 8)) & 0xFFu;
}
__device__ __forceinline__ void setb(unsigned* lab, int q, unsigned v) {
    int sh = (q & 3) * 8;
    lab[q >> 2] = (lab[q >> 2] & ~(0xFFu << sh)) | (v << sh);
}

// ---------------- Phase 3: KIT fused iterations ----------------
// Thread = column. dist + labels + wg in registers; penalty maps cU/cL in
// DYNAMIC smem (read-only tiles; 50 KB > 48 KB static cap, hence extern).
// Vertical passes: pure-register Jacobi (sweep order => neighbor still old).
// Horizontal passes: dist/label neighbor via __shfl, warp boundaries via a
// small static double-buffered smem exchange; cpL[x-1] read directly from
// smem with free toroidal wrap. Exact reference add order (nd+wg)+cp.
template <bool LAST>
__global__ __launch_bounds__(NT, 2) void fused_reg_kernel(int ab, float* __restrict__ out_mask) {
    extern __shared__ float s_dyn[];
    float* scU = s_dyn;              // [TFY][NT]
    float* scL = s_dyn + TFY * NT;   // [TFY][NT]

    __shared__ float    sLd[2][NW][TFY];   // lane-0 dist (pre-L)  for L pass
    __shared__ unsigned sLl[2][NW][NLAB];
    __shared__ float    sRd[2][NW][TFY];   // lane-31 dist (post-L) for R pass
    __shared__ unsigned sRl[2][NW][NLAB];

    const float*         din  = ab ? g_dB : g_dA;
    float*               dout = ab ? g_dA : g_dB;
    const unsigned char* lin  = ab ? g_lB : g_lA;
    unsigned char*       lout = ab ? g_lA : g_lB;

    const int x    = threadIdx.x;
    const int lane = x & 31;
    const int wq   = x >> 5;
    const int wqn  = (wq + 1) % NW;        // right neighbor warp (for L)
    const int wqp  = (wq + NW - 1) % NW;   // left neighbor warp (for R)
    const int xl   = (x == 0) ? WW - 1 : x - 1;   // left column (wrapped)
    const int band = blockIdx.x;
    const int b    = blockIdx.y;
    const int bb   = b * HWP;
    const int y0   = band * BR - KIT;

    float    dist[TFY], wg[TFY];
    unsigned lab[NLAB];

    // ---- load (coalesced: fixed row, lanes = consecutive columns) ----
    #pragma unroll
    for (int r = 0; r < TFY; r++) {
        int gy = y0 + r; if (gy < 0) gy += HH; else if (gy >= HH) gy -= HH;
        int gi = bb + gy * WW + x;
        dist[r]       = din[gi];
        wg[r]         = g_wg [gi];
        scU[r*NT + x] = g_cpU[gi];
        scL[r*NT + x] = g_cpL[gi];
        unsigned lv = lin[gi];
        if ((r & 3) == 0) lab[r >> 2] = lv;
        else              lab[r >> 2] |= lv << ((r & 3) * 8);
    }
    // no sync needed yet: the first vertical passes touch only this thread's
    // own smem column (STS->LDS same thread is ordered); the first
    // __syncthreads below publishes scU/scL for cross-column reads.

    for (int i = 0; i < KIT; i++) {
        const int pb = i & 1;
        // ---- U: rows [i, TFY-1-i), ascending (reads r+1 old) ----
        #pragma unroll
        for (int r = 0; r < TFY - 1; r++) {
            if (r >= i && r < TFY - 1 - i) {
                float wd = (dist[r + 1] + wg[r]) + scU[r*NT + x];
                if (wd < dist[r]) { dist[r] = wd; setb(lab, r, getb(lab, r + 1)); }
            }
        }
        // ---- D: rows [i+1, TFY-1-i), descending (reads r-1 old) ----
        #pragma unroll
        for (int rr = 0; rr < TFY - 2; rr++) {
            int r = TFY - 2 - rr;
            if (r >= i + 1 && r < TFY - 1 - i) {
                float wd = (dist[r - 1] + wg[r]) + scU[(r-1)*NT + x];
                if (wd < dist[r]) { dist[r] = wd; setb(lab, r, getb(lab, r - 1)); }
            }
        }

        // ---- L boundary write (pre-L lane-0 state), sync ----
        if (lane == 0) {
            #pragma unroll
            for (int r = 0; r < TFY; r++) sLd[pb][wq][r] = dist[r];
            #pragma unroll
            for (int k = 0; k < NLAB; k++) sLl[pb][wq][k] = lab[k];
        }
        __syncthreads();
        // ---- L: reads column x+1 (old), rows [i+1, TFY-1-i) ----
        {
            unsigned nlab[NLAB];
            #pragma unroll
            for (int k = 0; k < NLAB; k++) {
                nlab[k] = __shfl_down_sync(0xffffffffu, lab[k], 1);
                if (lane == 31) nlab[k] = sLl[pb][wqn][k];
            }
            #pragma unroll
            for (int r = 1; r < TFY - 1; r++) {
                float nd = __shfl_down_sync(0xffffffffu, dist[r], 1);
                if (r >= i + 1 && r < TFY - 1 - i) {
                    if (lane == 31) nd = sLd[pb][wqn][r];
                    float wd = (nd + wg[r]) + scL[r*NT + x];
                    if (wd < dist[r]) { dist[r] = wd; setb(lab, r, getb(nlab, r)); }
                }
            }
        }
        // ---- R boundary write (post-L lane-31 state), sync ----
        if (lane == 31) {
            #pragma unroll
            for (int r = 0; r < TFY; r++) sRd[pb][wq][r] = dist[r];
            #pragma unroll
            for (int k = 0; k < NLAB; k++) sRl[pb][wq][k] = lab[k];
        }
        __syncthreads();
        // ---- R: reads column x-1 (post-L), cp = cpL[x-1] via smem ----
        {
            unsigned nlab[NLAB];
            #pragma unroll
            for (int k = 0; k < NLAB; k++) {
                nlab[k] = __shfl_up_sync(0xffffffffu, lab[k], 1);
                if (lane == 0) nlab[k] = sRl[pb][wqp][k];
            }
            #pragma unroll
            for (int r = 1; r < TFY - 1; r++) {
                float nd = __shfl_up_sync(0xffffffffu, dist[r], 1);
                if (r >= i + 1 && r < TFY - 1 - i) {
                    if (lane == 0) nd = sRd[pb][wqp][r];
                    float wd = (nd + wg[r]) + scL[r*NT + xl];
                    if (wd < dist[r]) { dist[r] = wd; setb(lab, r, getb(nlab, r)); }
                }
            }
        }
    }

    // ---- store interior rows [KIT, KIT+BR) (clipped at image edge) ----
    #pragma unroll
    for (int r = 0; r < BR; r++) {
        int gy = band * BR + r;
        if (gy < HH) {
            int gi = bb + gy * WW + x;
            unsigned v = getb(lab, KIT + r);
            if (LAST) {
                out_mask[gi] = (v == 255u) ? -1.0f : (float)v;
            } else {
                dout[gi] = dist[KIT + r];
                lout[gi] = (unsigned char)v;
            }
        }
    }
}

// ---------------- launch ----------------
extern "C" void kernel_launch(void* const* d_in, const int* in_sizes, int n_in,
                              void* d_out, int out_size) {
    const float* x;
    const float* g;
    if (in_sizes[0] == BB * 3 * HWP) { x = (const float*)d_in[0]; g = (const float*)d_in[1]; }
    else                             { x = (const float*)d_in[1]; g = (const float*)d_in[0]; }

    float* out       = (float*)d_out;
    float* out_cents = out;               // [B, C, 2] float32
    float* out_mask  = out + BB * CC * 2; // [B, H, W] float32

    const int NPX = BB * HWP;
    const int TPB = 256;
    const int GPX = (NPX + TPB - 1) / TPB;

    cudaFuncSetAttribute(fused_reg_kernel<false>,
                         cudaFuncAttributeMaxDynamicSharedMemorySize, DYN_SMEM);
    cudaFuncSetAttribute(fused_reg_kernel<true>,
                         cudaFuncAttributeMaxDynamicSharedMemorySize, DYN_SMEM);

    minima_kernel<<<(BB * CC * 32 + TPB - 1) / TPB, TPB>>>(g);
    resolve_kernel<<<BB, 32>>>(g, out_cents);
    maps_kernel<<<GPX, TPB>>>(x, g);
    seed_kernel<<<(BB * CC + TPB - 1) / TPB, TPB>>>();

    int ab = 0;   // 0: current state in A
    const int NLAUNCH = 50 / KIT;   // 10
    for (int k = 0; k < NLAUNCH - 1; k++) {
        fused_reg_kernel<false><<<dim3(BANDS, BB), NT, DYN_SMEM>>>(ab, out_mask);
        ab ^= 1;
    }
    fused_reg_kernel<true><<<dim3(BANDS, BB), NT, DYN_SMEM>>>(ab, out_mask);
}